// round 3
// baseline (speedup 1.0000x reference)
#include <cuda_runtime.h>
#include <cuda_fp16.h>
#include <cuda_bf16.h>
#include <cstdint>

// Problem constants (fixed shapes)
#define NN 100000
#define NE 3200000
#define NG 1024
#define H  128
#define ND 32
#define ED 16
#define NL 3

// ---------------- device scratch (allocation-free: __device__ globals) ----------------
// EH stored as fp16 (half2 pairs), dst-sorted order: NE * 64 half2 = 819 MB
__device__ __half2 g_EH[(size_t)NE * (H / 2)];
__device__ float   g_Xa[(size_t)NN * H];   // ping
__device__ float   g_Xb[(size_t)NN * H];   // pong
__device__ int     g_cnt[NN];
__device__ int     g_cur[NN];
__device__ int     g_rowptr[NN + 1];
__device__ int     g_ssrc[NE];             // src node of sorted edge
__device__ int     g_seid[NE];             // original edge id of sorted edge

__device__ __forceinline__ float4 ldcs4(const float* p) {
    return __ldcs((const float4*)p);
}

// ---------------- 0: zero counters ----------------
__global__ void zero_kernel() {
    int i = blockIdx.x * blockDim.x + threadIdx.x;
    int stride = gridDim.x * blockDim.x;
    for (; i < NN; i += stride) { g_cnt[i] = 0; g_cur[i] = 0; }
}

// ---------------- 1: histogram of dst ----------------
__global__ void hist_kernel(const int* __restrict__ ei) {
    int i = blockIdx.x * blockDim.x + threadIdx.x;
    int stride = gridDim.x * blockDim.x;
    for (; i < NE; i += stride) {
        int d = __ldcs(&ei[NE + i]);
        atomicAdd(&g_cnt[d], 1);
    }
}

// ---------------- 2: exclusive scan (single block, 1024 threads, shuffle scan) -------
__global__ void scan_kernel() {
    __shared__ int wsum[32];
    __shared__ int carry_s;
    const int tid = threadIdx.x, lane = tid & 31, wid = tid >> 5;
    if (tid == 0) carry_s = 0;
    __syncthreads();
    for (int base = 0; base < NN; base += 1024) {
        int i = base + tid;
        int v = (i < NN) ? g_cnt[i] : 0;
        int incl = v;
        #pragma unroll
        for (int off = 1; off < 32; off <<= 1) {
            int t = __shfl_up_sync(0xffffffffu, incl, off);
            if (lane >= off) incl += t;
        }
        if (lane == 31) wsum[wid] = incl;
        __syncthreads();
        if (wid == 0) {
            int s = wsum[lane];
            int si = s;
            #pragma unroll
            for (int off = 1; off < 32; off <<= 1) {
                int t = __shfl_up_sync(0xffffffffu, si, off);
                if (lane >= off) si += t;
            }
            wsum[lane] = si - s;   // exclusive warp offsets
        }
        __syncthreads();
        int excl = carry_s + wsum[wid] + incl - v;
        if (i < NN) g_rowptr[i] = excl;
        __syncthreads();                              // everyone has read carry_s / wsum
        if (tid == 1023) carry_s += wsum[31] + incl;  // chunk total
        __syncthreads();
    }
    if (threadIdx.x == 0) g_rowptr[NN] = carry_s;
}

// ---------------- 3: scatter edges into dst-sorted order ----------------
__global__ void scatter_kernel(const int* __restrict__ ei) {
    int i = blockIdx.x * blockDim.x + threadIdx.x;
    int stride = gridDim.x * blockDim.x;
    for (; i < NE; i += stride) {
        int s = __ldcs(&ei[i]);
        int d = __ldcs(&ei[NE + i]);
        int p = atomicAdd(&g_cur[d], 1);
        int idx = g_rowptr[d] + p;
        g_ssrc[idx] = s;
        g_seid[idx] = i;
    }
}

// ---------------- 4: edge encoder, written fp16 in SORTED order -------------------
// One warp handles 8 sorted positions per iteration: e_h = ef @ W_edge + b_edge
__global__ __launch_bounds__(256) void edge_enc_kernel(
    const float* __restrict__ ef, const float* __restrict__ We, const float* __restrict__ be)
{
    __shared__ float Ws[ED * H];           // 8 KB
    __shared__ float efb[8][ED * 8];       // per warp: [k][j], 8 edges

    const int tid = threadIdx.x;
    for (int i = tid; i < ED * H; i += blockDim.x) Ws[i] = We[i];
    __syncthreads();

    const int lane = tid & 31, w = tid >> 5;
    const int warpGlobal = blockIdx.x * (blockDim.x >> 5) + w;
    const int nwarps = gridDim.x * (blockDim.x >> 5);
    const float4 bias = *(const float4*)&be[lane * 4];
    float* eb = &efb[w][0];

    const int ngroups = NE / 8;            // 400000, exact
    for (int g = warpGlobal; g < ngroups; g += nwarps) {
        const int i0 = g * 8;
        // load edge feature rows: lane -> edge j = lane/4, quad q = lane%4
        const int j = lane >> 2, q = lane & 3;
        const int eid = __ldcs(&g_seid[i0 + j]);
        const float4 v = ldcs4(&ef[(size_t)eid * ED + q * 4]);
        eb[(q * 4 + 0) * 8 + j] = v.x;
        eb[(q * 4 + 1) * 8 + j] = v.y;
        eb[(q * 4 + 2) * 8 + j] = v.z;
        eb[(q * 4 + 3) * 8 + j] = v.w;
        __syncwarp();

        float a[8][4];
        #pragma unroll
        for (int jj = 0; jj < 8; jj++) {
            a[jj][0] = bias.x; a[jj][1] = bias.y; a[jj][2] = bias.z; a[jj][3] = bias.w;
        }
        #pragma unroll
        for (int k = 0; k < ED; k++) {
            const float4 w4  = *(const float4*)&Ws[k * H + lane * 4];
            const float4 e03 = *(const float4*)&eb[k * 8];
            const float4 e47 = *(const float4*)&eb[k * 8 + 4];
            const float hv[8] = {e03.x, e03.y, e03.z, e03.w, e47.x, e47.y, e47.z, e47.w};
            #pragma unroll
            for (int jj = 0; jj < 8; jj++) {
                a[jj][0] += hv[jj] * w4.x; a[jj][1] += hv[jj] * w4.y;
                a[jj][2] += hv[jj] * w4.z; a[jj][3] += hv[jj] * w4.w;
            }
        }
        __syncwarp();
        #pragma unroll
        for (int jj = 0; jj < 8; jj++) {
            __half2 h0 = __floats2half2_rn(a[jj][0], a[jj][1]);
            __half2 h1 = __floats2half2_rn(a[jj][2], a[jj][3]);
            uint2 u;
            u.x = *reinterpret_cast<unsigned int*>(&h0);
            u.y = *reinterpret_cast<unsigned int*>(&h1);
            // streaming store (no reuse until layer pass); 8 B per lane, 256 B per warp row
            __stcs((uint2*)&g_EH[(size_t)(i0 + jj) * (H / 2) + lane * 2], u);
        }
    }
}

// ---------------- 5: node encoder: X = relu(nf @ W_node + b_node) -------------
__global__ __launch_bounds__(256) void node_enc_kernel(
    const float* __restrict__ nf, const float* __restrict__ Wn, const float* __restrict__ bn)
{
    __shared__ float Ws[ND * H];          // 16 KB
    __shared__ float nb[8][ND * 4];       // per warp: [k][j], 4 nodes

    const int tid = threadIdx.x;
    for (int i = tid; i < ND * H; i += blockDim.x) Ws[i] = Wn[i];
    __syncthreads();

    const int lane = tid & 31, w = tid >> 5;
    const int warpGlobal = blockIdx.x * (blockDim.x >> 5) + w;
    const int nwarps = gridDim.x * (blockDim.x >> 5);
    const float4 bias = *(const float4*)&bn[lane * 4];
    float* b = &nb[w][0];

    const int ngroups = NN / 4;           // 25000, exact
    for (int g = warpGlobal; g < ngroups; g += nwarps) {
        const int n0 = g * 4;
        // lane -> node j = lane/8, quad q = lane%8
        const int j = lane >> 3, q = lane & 7;
        const float4 v = *(const float4*)&nf[(size_t)(n0 + j) * ND + q * 4];
        b[(q * 4 + 0) * 4 + j] = v.x;
        b[(q * 4 + 1) * 4 + j] = v.y;
        b[(q * 4 + 2) * 4 + j] = v.z;
        b[(q * 4 + 3) * 4 + j] = v.w;
        __syncwarp();

        float a[4][4];
        #pragma unroll
        for (int jj = 0; jj < 4; jj++) {
            a[jj][0] = bias.x; a[jj][1] = bias.y; a[jj][2] = bias.z; a[jj][3] = bias.w;
        }
        #pragma unroll
        for (int k = 0; k < ND; k++) {
            const float4 w4 = *(const float4*)&Ws[k * H + lane * 4];
            const float4 h4 = *(const float4*)&b[k * 4];
            const float hv[4] = {h4.x, h4.y, h4.z, h4.w};
            #pragma unroll
            for (int jj = 0; jj < 4; jj++) {
                a[jj][0] += hv[jj] * w4.x; a[jj][1] += hv[jj] * w4.y;
                a[jj][2] += hv[jj] * w4.z; a[jj][3] += hv[jj] * w4.w;
            }
        }
        __syncwarp();
        #pragma unroll
        for (int jj = 0; jj < 4; jj++) {
            float4 r = make_float4(fmaxf(a[jj][0], 0.f), fmaxf(a[jj][1], 0.f),
                                   fmaxf(a[jj][2], 0.f), fmaxf(a[jj][3], 0.f));
            *(float4*)&g_Xa[(size_t)(n0 + jj) * H + lane * 4] = r;
        }
    }
}

// ---------------- 6: fused GINE layer: agg + MLP(128->128 relu ->128) + relu --
// One warp processes 8 nodes per group. h staged in shared, 8-wide matvec.
// EH (fp16) / ssrc are streamed (__ldcs) so the Xin gather set stays L2-resident.
__global__ __launch_bounds__(256) void layer_kernel(
    const float* __restrict__ Xin, float* __restrict__ Xout,
    const float* __restrict__ w1, const float* __restrict__ b1,
    const float* __restrict__ w2, const float* __restrict__ b2,
    const float* __restrict__ eps_arr, int l)
{
    __shared__ float hb[8][H * 8];        // 8 warps * 4 KB = 32 KB

    const int tid = threadIdx.x, lane = tid & 31, w = tid >> 5;
    const int warpGlobal = blockIdx.x * (blockDim.x >> 5) + w;
    const int nwarps = gridDim.x * (blockDim.x >> 5);
    const float epsp1 = 1.0f + eps_arr[l];
    float* hbuf = &hb[w][0];

    const float4 b1v = *(const float4*)&b1[lane * 4];
    const float4 b2v = *(const float4*)&b2[lane * 4];

    const int ngroups = NN / 8;           // 12500, exact
    for (int g = warpGlobal; g < ngroups; g += nwarps) {
        const int n0 = g * 8;

        // ---- aggregation for 8 nodes ----
        for (int j = 0; j < 8; j++) {
            const int n = n0 + j;
            const int rs = g_rowptr[n], re = g_rowptr[n + 1];
            float4 acc = make_float4(0.f, 0.f, 0.f, 0.f);
            for (int i = rs; i < re; i++) {
                const int s = __ldcs(&g_ssrc[i]);
                const float4 xs = *(const float4*)&Xin[(size_t)s * H + lane * 4];
                const uint2 u = __ldcs((const uint2*)&g_EH[(size_t)i * (H / 2) + lane * 2]);
                const float2 e01 = __half22float2(*reinterpret_cast<const __half2*>(&u.x));
                const float2 e23 = __half22float2(*reinterpret_cast<const __half2*>(&u.y));
                acc.x += fmaxf(xs.x + e01.x, 0.f);
                acc.y += fmaxf(xs.y + e01.y, 0.f);
                acc.z += fmaxf(xs.z + e23.x, 0.f);
                acc.w += fmaxf(xs.w + e23.y, 0.f);
            }
            const float4 xn = *(const float4*)&Xin[(size_t)n * H + lane * 4];
            const float4 h = make_float4(epsp1 * xn.x + acc.x, epsp1 * xn.y + acc.y,
                                         epsp1 * xn.z + acc.z, epsp1 * xn.w + acc.w);
            hbuf[(lane * 4 + 0) * 8 + j] = h.x;
            hbuf[(lane * 4 + 1) * 8 + j] = h.y;
            hbuf[(lane * 4 + 2) * 8 + j] = h.z;
            hbuf[(lane * 4 + 3) * 8 + j] = h.w;
        }
        __syncwarp();

        // ---- GEMM1: y1 = relu(h @ w1 + b1) ----
        float a[8][4];
        #pragma unroll
        for (int jj = 0; jj < 8; jj++) {
            a[jj][0] = b1v.x; a[jj][1] = b1v.y; a[jj][2] = b1v.z; a[jj][3] = b1v.w;
        }
        #pragma unroll 4
        for (int k = 0; k < H; k++) {
            const float4 w4  = *(const float4*)&w1[k * H + lane * 4];
            const float4 h03 = *(const float4*)&hbuf[k * 8];
            const float4 h47 = *(const float4*)&hbuf[k * 8 + 4];
            const float hv[8] = {h03.x, h03.y, h03.z, h03.w, h47.x, h47.y, h47.z, h47.w};
            #pragma unroll
            for (int jj = 0; jj < 8; jj++) {
                a[jj][0] += hv[jj] * w4.x; a[jj][1] += hv[jj] * w4.y;
                a[jj][2] += hv[jj] * w4.z; a[jj][3] += hv[jj] * w4.w;
            }
        }
        __syncwarp();
        // write relu(y1) back over hbuf
        #pragma unroll
        for (int jj = 0; jj < 8; jj++) {
            hbuf[(lane * 4 + 0) * 8 + jj] = fmaxf(a[jj][0], 0.f);
            hbuf[(lane * 4 + 1) * 8 + jj] = fmaxf(a[jj][1], 0.f);
            hbuf[(lane * 4 + 2) * 8 + jj] = fmaxf(a[jj][2], 0.f);
            hbuf[(lane * 4 + 3) * 8 + jj] = fmaxf(a[jj][3], 0.f);
        }
        __syncwarp();

        // ---- GEMM2: x = relu(y1 @ w2 + b2) ----
        #pragma unroll
        for (int jj = 0; jj < 8; jj++) {
            a[jj][0] = b2v.x; a[jj][1] = b2v.y; a[jj][2] = b2v.z; a[jj][3] = b2v.w;
        }
        #pragma unroll 4
        for (int k = 0; k < H; k++) {
            const float4 w4  = *(const float4*)&w2[k * H + lane * 4];
            const float4 h03 = *(const float4*)&hbuf[k * 8];
            const float4 h47 = *(const float4*)&hbuf[k * 8 + 4];
            const float hv[8] = {h03.x, h03.y, h03.z, h03.w, h47.x, h47.y, h47.z, h47.w};
            #pragma unroll
            for (int jj = 0; jj < 8; jj++) {
                a[jj][0] += hv[jj] * w4.x; a[jj][1] += hv[jj] * w4.y;
                a[jj][2] += hv[jj] * w4.z; a[jj][3] += hv[jj] * w4.w;
            }
        }
        __syncwarp();
        #pragma unroll
        for (int jj = 0; jj < 8; jj++) {
            float4 r = make_float4(fmaxf(a[jj][0], 0.f), fmaxf(a[jj][1], 0.f),
                                   fmaxf(a[jj][2], 0.f), fmaxf(a[jj][3], 0.f));
            *(float4*)&Xout[(size_t)(n0 + jj) * H + lane * 4] = r;
        }
    }
}

// ---------------- 7: pool (batch is sorted!) + readout MLP ----------------
__global__ __launch_bounds__(128) void readout_kernel(
    const float* __restrict__ Xin, const int* __restrict__ batch,
    const float* __restrict__ fw1, const float* __restrict__ fb1,
    const float* __restrict__ fw2, const float* __restrict__ fb2,
    float* __restrict__ out)
{
    const int g = blockIdx.x;
    const int tid = threadIdx.x;
    __shared__ float pool[H];
    __shared__ int   se[2];
    __shared__ float red[H];

    if (tid < 2) {
        const int target = g + tid;
        int lo = 0, hi = NN;
        while (lo < hi) { int mid = (lo + hi) >> 1; if (batch[mid] < target) lo = mid + 1; else hi = mid; }
        se[tid] = lo;
    }
    __syncthreads();
    const int start = se[0], end = se[1];

    float sum = 0.f;
    for (int n = start; n < end; n++) sum += Xin[(size_t)n * H + tid];
    const int cnt = end - start;
    pool[tid] = sum / (float)max(cnt, 1);
    __syncthreads();

    float acc = fb1[tid];
    #pragma unroll 4
    for (int k = 0; k < H; k++) acc += pool[k] * fw1[k * H + tid];
    acc = fmaxf(acc, 0.f);

    red[tid] = acc * fw2[tid];
    __syncthreads();
    for (int off = 64; off > 0; off >>= 1) {
        if (tid < off) red[tid] += red[tid + off];
        __syncthreads();
    }
    if (tid == 0) out[g] = red[0] + fb2[0];
}

// ---------------- launch ----------------
extern "C" void kernel_launch(void* const* d_in, const int* in_sizes, int n_in,
                              void* d_out, int out_size)
{
    const float* nf   = (const float*)d_in[0];
    const float* ef   = (const float*)d_in[1];
    const int*   ei   = (const int*)  d_in[2];
    const int*   bat  = (const int*)  d_in[3];
    const float* Wn   = (const float*)d_in[4];
    const float* bn   = (const float*)d_in[5];
    const float* We   = (const float*)d_in[6];
    const float* be   = (const float*)d_in[7];
    const float* cw1  = (const float*)d_in[8];
    const float* cb1  = (const float*)d_in[9];
    const float* cw2  = (const float*)d_in[10];
    const float* cb2  = (const float*)d_in[11];
    const float* eps  = (const float*)d_in[12];
    const float* fw1  = (const float*)d_in[13];
    const float* fb1  = (const float*)d_in[14];
    const float* fw2  = (const float*)d_in[15];
    const float* fb2  = (const float*)d_in[16];
    float* out = (float*)d_out;

    float* Xa = nullptr; float* Xb = nullptr;
    cudaGetSymbolAddress((void**)&Xa, g_Xa);
    cudaGetSymbolAddress((void**)&Xb, g_Xb);

    // CSR build
    zero_kernel   <<<784, 256>>>();
    hist_kernel   <<<2048, 256>>>(ei);
    scan_kernel   <<<1, 1024>>>();
    scatter_kernel<<<2048, 256>>>(ei);

    // encoders
    edge_enc_kernel<<<1600, 256>>>(ef, We, be);
    node_enc_kernel<<<800, 256>>>(nf, Wn, bn);

    // 3 GINE layers (ping-pong)
    layer_kernel<<<888, 256>>>(Xa, Xb, cw1 + 0 * H * H, cb1 + 0 * H, cw2 + 0 * H * H, cb2 + 0 * H, eps, 0);
    layer_kernel<<<888, 256>>>(Xb, Xa, cw1 + 1 * H * H, cb1 + 1 * H, cw2 + 1 * H * H, cb2 + 1 * H, eps, 1);
    layer_kernel<<<888, 256>>>(Xa, Xb, cw1 + 2 * H * H, cb1 + 2 * H, cw2 + 2 * H * H, cb2 + 2 * H, eps, 2);

    // pool + readout
    readout_kernel<<<NG, 128>>>(Xb, bat, fw1, fb1, fw2, fb2, out);

    (void)in_sizes; (void)n_in; (void)out_size;
}

// round 4
// speedup vs baseline: 1.2184x; 1.2184x over previous
#include <cuda_runtime.h>
#include <cuda_fp16.h>
#include <cuda_bf16.h>
#include <cstdint>

// Problem constants (fixed shapes)
#define NN 100000
#define NE 3200000
#define NG 1024
#define H  128
#define ND 32
#define ED 16
#define NL 3

// ---------------- device scratch (allocation-free: __device__ globals) ----------------
__device__ __half g_EH[(size_t)NE * H];    // edge-encoded features fp16, dst-sorted (819 MB)
__device__ __half g_Xa[(size_t)NN * H];    // ping (fp16)
__device__ __half g_Xb[(size_t)NN * H];    // pong (fp16)
__device__ int    g_cnt[NN];
__device__ int    g_cur[NN];
__device__ int    g_rowptr[NN + 1];
__device__ uint2  g_sedge[NE];             // {src, original edge id} per sorted slot

__device__ __forceinline__ float4 ldcs4(const float* p) {
    return __ldcs((const float4*)p);
}

// ---- packed f32x2 helpers (FFMA2: 2 MACs per issued instruction) ----
__device__ __forceinline__ unsigned long long pack2f(float lo, float hi) {
    unsigned long long r;
    asm("mov.b64 %0, {%1, %2};" : "=l"(r) : "f"(lo), "f"(hi));
    return r;
}
__device__ __forceinline__ float2 unpack2f(unsigned long long v) {
    float lo, hi;
    asm("mov.b64 {%0, %1}, %2;" : "=f"(lo), "=f"(hi) : "l"(v));
    return make_float2(lo, hi);
}
__device__ __forceinline__ void ffma2(unsigned long long& d,
                                      unsigned long long a, unsigned long long b) {
    asm("fma.rn.f32x2 %0, %1, %2, %0;" : "+l"(d) : "l"(a), "l"(b));
}

__device__ __forceinline__ __half2 u2h2(unsigned int u) {
    return *reinterpret_cast<const __half2*>(&u);
}

// ---------------- 0: zero counters ----------------
__global__ void zero_kernel() {
    int i = blockIdx.x * blockDim.x + threadIdx.x;
    int stride = gridDim.x * blockDim.x;
    for (; i < NN; i += stride) { g_cnt[i] = 0; g_cur[i] = 0; }
}

// ---------------- 1: histogram of dst ----------------
__global__ void hist_kernel(const int* __restrict__ ei) {
    int i = blockIdx.x * blockDim.x + threadIdx.x;
    int stride = gridDim.x * blockDim.x;
    for (; i < NE; i += stride) {
        int d = __ldcs(&ei[NE + i]);
        atomicAdd(&g_cnt[d], 1);
    }
}

// ---------------- 2: exclusive scan (single block, 1024 threads) ----------------
__global__ void scan_kernel() {
    __shared__ int wsum[32];
    __shared__ int carry_s;
    const int tid = threadIdx.x, lane = tid & 31, wid = tid >> 5;
    if (tid == 0) carry_s = 0;
    __syncthreads();
    for (int base = 0; base < NN; base += 1024) {
        int i = base + tid;
        int v = (i < NN) ? g_cnt[i] : 0;
        int incl = v;
        #pragma unroll
        for (int off = 1; off < 32; off <<= 1) {
            int t = __shfl_up_sync(0xffffffffu, incl, off);
            if (lane >= off) incl += t;
        }
        if (lane == 31) wsum[wid] = incl;
        __syncthreads();
        if (wid == 0) {
            int s = wsum[lane];
            int si = s;
            #pragma unroll
            for (int off = 1; off < 32; off <<= 1) {
                int t = __shfl_up_sync(0xffffffffu, si, off);
                if (lane >= off) si += t;
            }
            wsum[lane] = si - s;
        }
        __syncthreads();
        int excl = carry_s + wsum[wid] + incl - v;
        if (i < NN) g_rowptr[i] = excl;
        __syncthreads();
        if (tid == 1023) carry_s += wsum[31] + incl;
        __syncthreads();
    }
    if (threadIdx.x == 0) g_rowptr[NN] = carry_s;
}

// ---------------- 3: scatter edges into dst-sorted order (one 8B store) ---------
__global__ void scatter_kernel(const int* __restrict__ ei) {
    int i = blockIdx.x * blockDim.x + threadIdx.x;
    int stride = gridDim.x * blockDim.x;
    for (; i < NE; i += stride) {
        int s = __ldcs(&ei[i]);
        int d = __ldcs(&ei[NE + i]);
        int p = atomicAdd(&g_cur[d], 1);
        g_sedge[g_rowptr[d] + p] = make_uint2((unsigned)s, (unsigned)i);
    }
}

// ---------------- 4: edge encoder (FFMA2), fp16 output in sorted order ----------
__global__ __launch_bounds__(256) void edge_enc_kernel(
    const float* __restrict__ ef, const float* __restrict__ We, const float* __restrict__ be)
{
    __shared__ float Ws[ED * H];           // 8 KB
    __shared__ float efb[8][ED * 8];       // per warp: [k][j], 8 edges

    const int tid = threadIdx.x;
    for (int i = tid; i < ED * H; i += blockDim.x) Ws[i] = We[i];
    __syncthreads();

    const int lane = tid & 31, w = tid >> 5;
    const int warpGlobal = blockIdx.x * (blockDim.x >> 5) + w;
    const int nwarps = gridDim.x * (blockDim.x >> 5);
    const float4 bias = *(const float4*)&be[lane * 4];
    const unsigned long long blo = pack2f(bias.x, bias.y);
    const unsigned long long bhi = pack2f(bias.z, bias.w);
    float* eb = &efb[w][0];

    const int ngroups = NE / 8;            // 400000, exact
    for (int g = warpGlobal; g < ngroups; g += nwarps) {
        const int i0 = g * 8;
        const int j = lane >> 2, q = lane & 3;
        const unsigned eid = __ldcs(&g_sedge[i0 + j].y);
        const float4 v = ldcs4(&ef[(size_t)eid * ED + q * 4]);
        eb[(q * 4 + 0) * 8 + j] = v.x;
        eb[(q * 4 + 1) * 8 + j] = v.y;
        eb[(q * 4 + 2) * 8 + j] = v.z;
        eb[(q * 4 + 3) * 8 + j] = v.w;
        __syncwarp();

        unsigned long long a[8][2];
        #pragma unroll
        for (int jj = 0; jj < 8; jj++) { a[jj][0] = blo; a[jj][1] = bhi; }
        #pragma unroll
        for (int k = 0; k < ED; k++) {
            const float4 w4 = *(const float4*)&Ws[k * H + lane * 4];
            const unsigned long long wlo = pack2f(w4.x, w4.y);
            const unsigned long long whi = pack2f(w4.z, w4.w);
            const float4 e03 = *(const float4*)&eb[k * 8];
            const float4 e47 = *(const float4*)&eb[k * 8 + 4];
            const float hv[8] = {e03.x, e03.y, e03.z, e03.w, e47.x, e47.y, e47.z, e47.w};
            #pragma unroll
            for (int jj = 0; jj < 8; jj++) {
                const unsigned long long h2 = pack2f(hv[jj], hv[jj]);
                ffma2(a[jj][0], h2, wlo);
                ffma2(a[jj][1], h2, whi);
            }
        }
        __syncwarp();
        #pragma unroll
        for (int jj = 0; jj < 8; jj++) {
            const float2 lo = unpack2f(a[jj][0]);
            const float2 hi = unpack2f(a[jj][1]);
            __half2 h0 = __floats2half2_rn(lo.x, lo.y);
            __half2 h1 = __floats2half2_rn(hi.x, hi.y);
            uint2 u;
            u.x = *reinterpret_cast<unsigned int*>(&h0);
            u.y = *reinterpret_cast<unsigned int*>(&h1);
            __stcs((uint2*)&g_EH[(size_t)(i0 + jj) * H + lane * 4], u);
        }
    }
}

// ---------------- 5: node encoder: X = relu(nf @ W_node + b_node), fp16 out -----
__global__ __launch_bounds__(256) void node_enc_kernel(
    const float* __restrict__ nf, const float* __restrict__ Wn, const float* __restrict__ bn)
{
    __shared__ float Ws[ND * H];          // 16 KB
    __shared__ float nb[8][ND * 4];       // per warp: [k][j], 4 nodes

    const int tid = threadIdx.x;
    for (int i = tid; i < ND * H; i += blockDim.x) Ws[i] = Wn[i];
    __syncthreads();

    const int lane = tid & 31, w = tid >> 5;
    const int warpGlobal = blockIdx.x * (blockDim.x >> 5) + w;
    const int nwarps = gridDim.x * (blockDim.x >> 5);
    const float4 bias = *(const float4*)&bn[lane * 4];
    float* b = &nb[w][0];

    const int ngroups = NN / 4;           // 25000, exact
    for (int g = warpGlobal; g < ngroups; g += nwarps) {
        const int n0 = g * 4;
        const int j = lane >> 3, q = lane & 7;
        const float4 v = *(const float4*)&nf[(size_t)(n0 + j) * ND + q * 4];
        b[(q * 4 + 0) * 4 + j] = v.x;
        b[(q * 4 + 1) * 4 + j] = v.y;
        b[(q * 4 + 2) * 4 + j] = v.z;
        b[(q * 4 + 3) * 4 + j] = v.w;
        __syncwarp();

        float a[4][4];
        #pragma unroll
        for (int jj = 0; jj < 4; jj++) {
            a[jj][0] = bias.x; a[jj][1] = bias.y; a[jj][2] = bias.z; a[jj][3] = bias.w;
        }
        #pragma unroll
        for (int k = 0; k < ND; k++) {
            const float4 w4 = *(const float4*)&Ws[k * H + lane * 4];
            const float4 h4 = *(const float4*)&b[k * 4];
            const float hv[4] = {h4.x, h4.y, h4.z, h4.w};
            #pragma unroll
            for (int jj = 0; jj < 4; jj++) {
                a[jj][0] += hv[jj] * w4.x; a[jj][1] += hv[jj] * w4.y;
                a[jj][2] += hv[jj] * w4.z; a[jj][3] += hv[jj] * w4.w;
            }
        }
        __syncwarp();
        #pragma unroll
        for (int jj = 0; jj < 4; jj++) {
            __half2 h0 = __floats2half2_rn(fmaxf(a[jj][0], 0.f), fmaxf(a[jj][1], 0.f));
            __half2 h1 = __floats2half2_rn(fmaxf(a[jj][2], 0.f), fmaxf(a[jj][3], 0.f));
            uint2 u;
            u.x = *reinterpret_cast<unsigned int*>(&h0);
            u.y = *reinterpret_cast<unsigned int*>(&h1);
            *(uint2*)&g_Xa[(size_t)(n0 + jj) * H + lane * 4] = u;
        }
    }
}

// ---------------- 6: fused GINE layer: agg(fp16 in) + MLP(FFMA2) + relu ---------
__global__ __launch_bounds__(256) void layer_kernel(
    const __half* __restrict__ Xin, __half* __restrict__ Xout,
    const float* __restrict__ w1, const float* __restrict__ b1,
    const float* __restrict__ w2, const float* __restrict__ b2,
    const float* __restrict__ eps_arr, int l)
{
    __shared__ float hb[8][H * 8];        // 8 warps * 4 KB = 32 KB

    const int tid = threadIdx.x, lane = tid & 31, w = tid >> 5;
    const int warpGlobal = blockIdx.x * (blockDim.x >> 5) + w;
    const int nwarps = gridDim.x * (blockDim.x >> 5);
    const float epsp1 = 1.0f + eps_arr[l];
    float* hbuf = &hb[w][0];

    const float4 b1v = *(const float4*)&b1[lane * 4];
    const float4 b2v = *(const float4*)&b2[lane * 4];
    const unsigned long long b1lo = pack2f(b1v.x, b1v.y), b1hi = pack2f(b1v.z, b1v.w);
    const unsigned long long b2lo = pack2f(b2v.x, b2v.y), b2hi = pack2f(b2v.z, b2v.w);
    const __half2 zero2 = __floats2half2_rn(0.f, 0.f);

    const int ngroups = NN / 8;           // 12500, exact
    for (int g = warpGlobal; g < ngroups; g += nwarps) {
        const int n0 = g * 8;

        // ---- aggregation for 8 nodes ----
        for (int j = 0; j < 8; j++) {
            const int n = n0 + j;
            const int rs = g_rowptr[n], re = g_rowptr[n + 1];
            float4 acc = make_float4(0.f, 0.f, 0.f, 0.f);
            for (int i = rs; i < re; i++) {
                const uint2 se = __ldcs(&g_sedge[i]);           // broadcast
                const uint2 xu = *(const uint2*)&Xin[(size_t)se.x * H + lane * 4];
                const uint2 eu = __ldcs((const uint2*)&g_EH[(size_t)i * H + lane * 4]);
                const __half2 s0 = __hmax2(__hadd2(u2h2(xu.x), u2h2(eu.x)), zero2);
                const __half2 s1 = __hmax2(__hadd2(u2h2(xu.y), u2h2(eu.y)), zero2);
                const float2 f0 = __half22float2(s0);
                const float2 f1 = __half22float2(s1);
                acc.x += f0.x; acc.y += f0.y; acc.z += f1.x; acc.w += f1.y;
            }
            const uint2 xnu = *(const uint2*)&Xin[(size_t)n * H + lane * 4];
            const float2 xn01 = __half22float2(u2h2(xnu.x));
            const float2 xn23 = __half22float2(u2h2(xnu.y));
            hbuf[(lane * 4 + 0) * 8 + j] = fmaf(epsp1, xn01.x, acc.x);
            hbuf[(lane * 4 + 1) * 8 + j] = fmaf(epsp1, xn01.y, acc.y);
            hbuf[(lane * 4 + 2) * 8 + j] = fmaf(epsp1, xn23.x, acc.z);
            hbuf[(lane * 4 + 3) * 8 + j] = fmaf(epsp1, xn23.y, acc.w);
        }
        __syncwarp();

        // ---- GEMM1: y1 = relu(h @ w1 + b1), FFMA2 ----
        unsigned long long a[8][2];
        #pragma unroll
        for (int jj = 0; jj < 8; jj++) { a[jj][0] = b1lo; a[jj][1] = b1hi; }
        #pragma unroll 4
        for (int k = 0; k < H; k++) {
            const float4 w4 = *(const float4*)&w1[k * H + lane * 4];
            const unsigned long long wlo = pack2f(w4.x, w4.y);
            const unsigned long long whi = pack2f(w4.z, w4.w);
            const float4 h03 = *(const float4*)&hbuf[k * 8];
            const float4 h47 = *(const float4*)&hbuf[k * 8 + 4];
            const float hv[8] = {h03.x, h03.y, h03.z, h03.w, h47.x, h47.y, h47.z, h47.w};
            #pragma unroll
            for (int jj = 0; jj < 8; jj++) {
                const unsigned long long h2 = pack2f(hv[jj], hv[jj]);
                ffma2(a[jj][0], h2, wlo);
                ffma2(a[jj][1], h2, whi);
            }
        }
        __syncwarp();
        #pragma unroll
        for (int jj = 0; jj < 8; jj++) {
            const float2 lo = unpack2f(a[jj][0]);
            const float2 hi = unpack2f(a[jj][1]);
            hbuf[(lane * 4 + 0) * 8 + jj] = fmaxf(lo.x, 0.f);
            hbuf[(lane * 4 + 1) * 8 + jj] = fmaxf(lo.y, 0.f);
            hbuf[(lane * 4 + 2) * 8 + jj] = fmaxf(hi.x, 0.f);
            hbuf[(lane * 4 + 3) * 8 + jj] = fmaxf(hi.y, 0.f);
        }
        __syncwarp();

        // ---- GEMM2: x = relu(y1 @ w2 + b2), FFMA2 ----
        #pragma unroll
        for (int jj = 0; jj < 8; jj++) { a[jj][0] = b2lo; a[jj][1] = b2hi; }
        #pragma unroll 4
        for (int k = 0; k < H; k++) {
            const float4 w4 = *(const float4*)&w2[k * H + lane * 4];
            const unsigned long long wlo = pack2f(w4.x, w4.y);
            const unsigned long long whi = pack2f(w4.z, w4.w);
            const float4 h03 = *(const float4*)&hbuf[k * 8];
            const float4 h47 = *(const float4*)&hbuf[k * 8 + 4];
            const float hv[8] = {h03.x, h03.y, h03.z, h03.w, h47.x, h47.y, h47.z, h47.w};
            #pragma unroll
            for (int jj = 0; jj < 8; jj++) {
                const unsigned long long h2 = pack2f(hv[jj], hv[jj]);
                ffma2(a[jj][0], h2, wlo);
                ffma2(a[jj][1], h2, whi);
            }
        }
        __syncwarp();
        #pragma unroll
        for (int jj = 0; jj < 8; jj++) {
            const float2 lo = unpack2f(a[jj][0]);
            const float2 hi = unpack2f(a[jj][1]);
            __half2 h0 = __floats2half2_rn(fmaxf(lo.x, 0.f), fmaxf(lo.y, 0.f));
            __half2 h1 = __floats2half2_rn(fmaxf(hi.x, 0.f), fmaxf(hi.y, 0.f));
            uint2 u;
            u.x = *reinterpret_cast<unsigned int*>(&h0);
            u.y = *reinterpret_cast<unsigned int*>(&h1);
            *(uint2*)&Xout[(size_t)(n0 + jj) * H + lane * 4] = u;
        }
    }
}

// ---------------- 7: pool (batch is sorted!) + readout MLP ----------------
__global__ __launch_bounds__(128) void readout_kernel(
    const __half* __restrict__ Xin, const int* __restrict__ batch,
    const float* __restrict__ fw1, const float* __restrict__ fb1,
    const float* __restrict__ fw2, const float* __restrict__ fb2,
    float* __restrict__ out)
{
    const int g = blockIdx.x;
    const int tid = threadIdx.x;
    __shared__ float pool[H];
    __shared__ int   se[2];
    __shared__ float red[H];

    if (tid < 2) {
        const int target = g + tid;
        int lo = 0, hi = NN;
        while (lo < hi) { int mid = (lo + hi) >> 1; if (batch[mid] < target) lo = mid + 1; else hi = mid; }
        se[tid] = lo;
    }
    __syncthreads();
    const int start = se[0], end = se[1];

    float sum = 0.f;
    for (int n = start; n < end; n++) sum += __half2float(Xin[(size_t)n * H + tid]);
    const int cnt = end - start;
    pool[tid] = sum / (float)max(cnt, 1);
    __syncthreads();

    float acc = fb1[tid];
    #pragma unroll 4
    for (int k = 0; k < H; k++) acc += pool[k] * fw1[k * H + tid];
    acc = fmaxf(acc, 0.f);

    red[tid] = acc * fw2[tid];
    __syncthreads();
    for (int off = 64; off > 0; off >>= 1) {
        if (tid < off) red[tid] += red[tid + off];
        __syncthreads();
    }
    if (tid == 0) out[g] = red[0] + fb2[0];
}

// ---------------- launch ----------------
extern "C" void kernel_launch(void* const* d_in, const int* in_sizes, int n_in,
                              void* d_out, int out_size)
{
    const float* nf   = (const float*)d_in[0];
    const float* ef   = (const float*)d_in[1];
    const int*   ei   = (const int*)  d_in[2];
    const int*   bat  = (const int*)  d_in[3];
    const float* Wn   = (const float*)d_in[4];
    const float* bn   = (const float*)d_in[5];
    const float* We   = (const float*)d_in[6];
    const float* be   = (const float*)d_in[7];
    const float* cw1  = (const float*)d_in[8];
    const float* cb1  = (const float*)d_in[9];
    const float* cw2  = (const float*)d_in[10];
    const float* cb2  = (const float*)d_in[11];
    const float* eps  = (const float*)d_in[12];
    const float* fw1  = (const float*)d_in[13];
    const float* fb1  = (const float*)d_in[14];
    const float* fw2  = (const float*)d_in[15];
    const float* fb2  = (const float*)d_in[16];
    float* out = (float*)d_out;

    __half* Xa = nullptr; __half* Xb = nullptr;
    cudaGetSymbolAddress((void**)&Xa, g_Xa);
    cudaGetSymbolAddress((void**)&Xb, g_Xb);

    // CSR build
    zero_kernel   <<<784, 256>>>();
    hist_kernel   <<<2048, 256>>>(ei);
    scan_kernel   <<<1, 1024>>>();
    scatter_kernel<<<2048, 256>>>(ei);

    // encoders
    edge_enc_kernel<<<1600, 256>>>(ef, We, be);
    node_enc_kernel<<<800, 256>>>(nf, Wn, bn);

    // 3 GINE layers (ping-pong)
    layer_kernel<<<888, 256>>>(Xa, Xb, cw1 + 0 * H * H, cb1 + 0 * H, cw2 + 0 * H * H, cb2 + 0 * H, eps, 0);
    layer_kernel<<<888, 256>>>(Xb, Xa, cw1 + 1 * H * H, cb1 + 1 * H, cw2 + 1 * H * H, cb2 + 1 * H, eps, 1);
    layer_kernel<<<888, 256>>>(Xa, Xb, cw1 + 2 * H * H, cb1 + 2 * H, cw2 + 2 * H * H, cb2 + 2 * H, eps, 2);

    // pool + readout
    readout_kernel<<<NG, 128>>>(Xb, bat, fw1, fb1, fw2, fb2, out);

    (void)in_sizes; (void)n_in; (void)out_size;
}